// round 2
// baseline (speedup 1.0000x reference)
#include <cuda_runtime.h>
#include <cuda_bf16.h>

#define N_NODES 100000
#define N_EDGES 1600000
#define CH      128   // in = out channels

// ---------------- static scratch (no allocations allowed) ----------------
__device__ float g_h1[(size_t)N_NODES * CH];
__device__ float g_h2[(size_t)N_NODES * CH];
__device__ int   g_deg[N_NODES];
__device__ int   g_off[N_NODES + 1];
__device__ int   g_cursor[N_NODES];
__device__ int   g_srcs[N_EDGES];
__device__ int   g_idx64;   // 1 if edge_index is int64, 0 if int32

// ---------------- dtype detection ----------------
// If edge_index is int64 (little-endian, values < 2^31), every odd 32-bit
// word is zero. If int32, odd words are random indices (almost surely != 0).
__global__ void k_detect(const int* __restrict__ raw) {
    int nz = 0;
#pragma unroll
    for (int i = 0; i < 64; i++) {
        if (raw[2 * i + 1] != 0) nz++;
    }
    g_idx64 = (nz == 0) ? 1 : 0;
}

__device__ __forceinline__ int load_idx(const void* ei, size_t pos) {
    if (g_idx64) {
        return (int)((const long long*)ei)[pos];
    } else {
        return ((const int*)ei)[pos];
    }
}

// ---------------- CSR build ----------------
__global__ void k_zero_deg() {
    int i = blockIdx.x * blockDim.x + threadIdx.x;
    if (i < N_NODES) g_deg[i] = 0;
}

__global__ void k_degree(const void* __restrict__ ei) {
    int e = blockIdx.x * blockDim.x + threadIdx.x;
    if (e < N_EDGES) {
        int d = load_idx(ei, (size_t)N_EDGES + e);  // dst row
        if (d >= 0 && d < N_NODES) atomicAdd(&g_deg[d], 1);
    }
}

// single-block exclusive scan of degrees -> offsets (and cursor copy)
__global__ void k_scan() {
    __shared__ int sums[1024];
    const int t = threadIdx.x;
    const int CHK = (N_NODES + 1023) / 1024;  // 98
    const int base = t * CHK;

    int s = 0;
    for (int i = 0; i < CHK; i++) {
        int idx = base + i;
        if (idx < N_NODES) s += g_deg[idx];
    }
    sums[t] = s;
    __syncthreads();
    // Hillis-Steele inclusive scan
    for (int off = 1; off < 1024; off <<= 1) {
        int v = (t >= off) ? sums[t - off] : 0;
        __syncthreads();
        sums[t] += v;
        __syncthreads();
    }
    int run = (t == 0) ? 0 : sums[t - 1];  // exclusive prefix
    for (int i = 0; i < CHK; i++) {
        int idx = base + i;
        if (idx < N_NODES) {
            g_off[idx] = run;
            g_cursor[idx] = run;
            run += g_deg[idx];
        }
    }
    if (t == 1023) g_off[N_NODES] = run;  // == N_EDGES (if all dst valid)
}

__global__ void k_fill(const void* __restrict__ ei) {
    int e = blockIdx.x * blockDim.x + threadIdx.x;
    if (e < N_EDGES) {
        int src = load_idx(ei, e);
        int dst = load_idx(ei, (size_t)N_EDGES + e);
        if (src >= 0 && src < N_NODES && dst >= 0 && dst < N_NODES) {
            int p = atomicAdd(&g_cursor[dst], 1);
            g_srcs[p] = src;
        }
    }
}

// ---------------- mean propagation: warp per dst node ----------------
__global__ void __launch_bounds__(256) k_hop(const float* __restrict__ in,
                                             float* __restrict__ out) {
    int warp = (blockIdx.x * blockDim.x + threadIdx.x) >> 5;
    int lane = threadIdx.x & 31;
    if (warp >= N_NODES) return;

    int beg = g_off[warp];
    int end = g_off[warp + 1];

    float4 acc0 = make_float4(0.f, 0.f, 0.f, 0.f);
    float4 acc1 = make_float4(0.f, 0.f, 0.f, 0.f);

    int j = beg;
    for (; j + 1 < end; j += 2) {
        int s0 = g_srcs[j];
        int s1 = g_srcs[j + 1];
        float4 v0 = __ldg((const float4*)(in + (size_t)s0 * CH) + lane);
        float4 v1 = __ldg((const float4*)(in + (size_t)s1 * CH) + lane);
        acc0.x += v0.x; acc0.y += v0.y; acc0.z += v0.z; acc0.w += v0.w;
        acc1.x += v1.x; acc1.y += v1.y; acc1.z += v1.z; acc1.w += v1.w;
    }
    if (j < end) {
        int s0 = g_srcs[j];
        float4 v0 = __ldg((const float4*)(in + (size_t)s0 * CH) + lane);
        acc0.x += v0.x; acc0.y += v0.y; acc0.z += v0.z; acc0.w += v0.w;
    }

    int d = end - beg;
    float inv = 1.0f / (float)(d > 0 ? d : 1);
    float4 r;
    r.x = (acc0.x + acc1.x) * inv;
    r.y = (acc0.y + acc1.y) * inv;
    r.z = (acc0.z + acc1.z) * inv;
    r.w = (acc0.w + acc1.w) * inv;
    ((float4*)(out + (size_t)warp * CH))[lane] = r;
}

// ---------------- GEMM: out = h @ W^T + b ----------------
// Each block handles 64 output columns (blockIdx.y selects the half) and a
// strip of rows. W half-tile lives in smem as Ws[k][oo] (128 x 64 floats, 32KB).
#define GEMM_WARPS 8
#define ROWS_PER_BLOCK 128

__global__ void __launch_bounds__(GEMM_WARPS * 32) k_gemm(
    const float* __restrict__ h, const float* __restrict__ W,
    const float* __restrict__ b, float* __restrict__ out) {
    __shared__ float Ws[128 * 64];

    const int t = threadIdx.x;
    const int warp = t >> 5;
    const int lane = t & 31;
    const int ho = blockIdx.y;              // 0 or 1: which 64 outputs
    const int obase = ho * 64;

    // load W half-tile, transposed to [k][oo]
    for (int idx = t; idx < 64 * 128; idx += GEMM_WARPS * 32) {
        int oo = idx >> 7;          // 0..63
        int k  = idx & 127;         // 0..127
        Ws[k * 64 + oo] = W[(size_t)(obase + oo) * CH + k];
    }
    const float b0 = __ldg(b + obase + 2 * lane);
    const float b1 = __ldg(b + obase + 2 * lane + 1);
    __syncthreads();

    const int rowBase = blockIdx.x * ROWS_PER_BLOCK;
    for (int rr = warp; rr < ROWS_PER_BLOCK; rr += GEMM_WARPS) {
        int n = rowBase + rr;
        if (n >= N_NODES) break;

        float4 hv = ((const float4*)(h + (size_t)n * CH))[lane];
        float hv4[4] = {hv.x, hv.y, hv.z, hv.w};

        float a0 = b0, a1 = b1;
#pragma unroll
        for (int k = 0; k < 128; k++) {
            float hk = __shfl_sync(0xffffffffu, hv4[k & 3], k >> 2);
            float2 w = *(const float2*)&Ws[k * 64 + 2 * lane];
            a0 = fmaf(hk, w.x, a0);
            a1 = fmaf(hk, w.y, a1);
        }
        float2 res = make_float2(a0, a1);
        *(float2*)(out + (size_t)n * CH + obase + 2 * lane) = res;
    }
}

// ---------------- launcher ----------------
extern "C" void kernel_launch(void* const* d_in, const int* in_sizes, int n_in,
                              void* d_out, int out_size) {
    const float* x  = (const float*)d_in[0];
    const void*  ei = d_in[1];   // int32 or int64, detected on device
    const float* W  = (const float*)d_in[2];
    const float* b  = (const float*)d_in[3];
    float*       out = (float*)d_out;

    const int TB = 256;

    // dtype detection + CSR build (every call: deterministic, capturable)
    k_detect<<<1, 1>>>((const int*)ei);
    k_zero_deg<<<(N_NODES + TB - 1) / TB, TB>>>();
    k_degree<<<(N_EDGES + TB - 1) / TB, TB>>>(ei);
    k_scan<<<1, 1024>>>();
    k_fill<<<(N_EDGES + TB - 1) / TB, TB>>>(ei);

    // two mean-propagation hops
    float* h1; float* h2;
    cudaGetSymbolAddress((void**)&h1, g_h1);
    cudaGetSymbolAddress((void**)&h2, g_h2);

    int hopBlocks = (N_NODES + 8 - 1) / 8;  // 8 warps per block, warp per node
    k_hop<<<hopBlocks, TB>>>(x,  h1);
    k_hop<<<hopBlocks, TB>>>(h1, h2);

    // final linear
    dim3 ggrid((N_NODES + ROWS_PER_BLOCK - 1) / ROWS_PER_BLOCK, 2);
    k_gemm<<<ggrid, GEMM_WARPS * 32>>>(h2, W, b, out);
}

// round 5
// speedup vs baseline: 2.2205x; 2.2205x over previous
#include <cuda_runtime.h>
#include <cuda_bf16.h>

#define N_NODES 100000
#define N_EDGES 1600000
#define CH      128   // in = out channels
#define N_SBLKS ((N_NODES + 1023) / 1024)   // 98

// ---------------- static scratch (no allocations allowed) ----------------
__device__ float g_h1[(size_t)N_NODES * CH];
__device__ float g_h2[(size_t)N_NODES * CH];
__device__ int   g_deg[N_NODES];
__device__ int   g_off[N_NODES + 1];
__device__ int   g_cursor[N_NODES];
__device__ int   g_srcs[N_EDGES];
__device__ int   g_part[128];
__device__ int   g_idx64;   // 1 if edge_index is int64, 0 if int32

// ---------------- dtype detection ----------------
// If edge_index is int64 (little-endian, values < 2^31), every odd 32-bit
// word is zero. If int32, odd words are random indices (almost surely != 0).
__global__ void k_detect(const int* __restrict__ raw) {
    int nz = 0;
#pragma unroll
    for (int i = 0; i < 64; i++) {
        if (raw[2 * i + 1] != 0) nz++;
    }
    g_idx64 = (nz == 0) ? 1 : 0;
}

__device__ __forceinline__ int load_idx(const void* ei, size_t pos) {
    if (g_idx64) {
        return (int)((const long long*)ei)[pos];
    } else {
        return ((const int*)ei)[pos];
    }
}

// ---------------- CSR build ----------------
__global__ void k_zero_deg() {
    int i = blockIdx.x * blockDim.x + threadIdx.x;
    if (i < N_NODES) g_deg[i] = 0;
}

__global__ void k_degree(const void* __restrict__ ei) {
    int e = blockIdx.x * blockDim.x + threadIdx.x;
    if (e < N_EDGES) {
        int d = load_idx(ei, (size_t)N_EDGES + e);  // dst row
        if (d >= 0 && d < N_NODES) atomicAdd(&g_deg[d], 1);
    }
}

// phase 1: per-block (1024 nodes) degree sums
__global__ void __launch_bounds__(1024) k_scan1() {
    int i = blockIdx.x * 1024 + threadIdx.x;
    int v = (i < N_NODES) ? g_deg[i] : 0;
#pragma unroll
    for (int o = 16; o; o >>= 1) v += __shfl_down_sync(0xffffffffu, v, o);
    __shared__ int ws[32];
    if ((threadIdx.x & 31) == 0) ws[threadIdx.x >> 5] = v;
    __syncthreads();
    if (threadIdx.x < 32) {
        int s = ws[threadIdx.x];
#pragma unroll
        for (int o = 16; o; o >>= 1) s += __shfl_down_sync(0xffffffffu, s, o);
        if (threadIdx.x == 0) g_part[blockIdx.x] = s;
    }
}

// phase 2: exclusive scan of the 98 partials (single tiny block)
__global__ void k_scan2() {
    int t = threadIdx.x;  // 128 threads
    __shared__ int sm[128];
    int v = (t < N_SBLKS) ? g_part[t] : 0;
    sm[t] = v;
    __syncthreads();
    for (int o = 1; o < 128; o <<= 1) {
        int u = (t >= o) ? sm[t - o] : 0;
        __syncthreads();
        sm[t] += u;
        __syncthreads();
    }
    g_part[t] = sm[t] - v;               // exclusive block offsets
    if (t == 127) g_off[N_NODES] = sm[127];
}

// phase 3: per-block exclusive scan + block offset -> g_off / g_cursor
__global__ void __launch_bounds__(1024) k_scan3() {
    int b = blockIdx.x, t = threadIdx.x;
    int i = b * 1024 + t;
    int lane = t & 31, w = t >> 5;
    int v = (i < N_NODES) ? g_deg[i] : 0;
    int s = v;
#pragma unroll
    for (int o = 1; o < 32; o <<= 1) {
        int u = __shfl_up_sync(0xffffffffu, s, o);
        if (lane >= o) s += u;
    }
    __shared__ int wsum[32];
    if (lane == 31) wsum[w] = s;
    __syncthreads();
    if (w == 0) {
        int ss = wsum[lane];
#pragma unroll
        for (int o = 1; o < 32; o <<= 1) {
            int u = __shfl_up_sync(0xffffffffu, ss, o);
            if (lane >= o) ss += u;
        }
        wsum[lane] = ss;   // inclusive warp sums
    }
    __syncthreads();
    int excl = (s - v) + ((w > 0) ? wsum[w - 1] : 0) + g_part[b];
    if (i < N_NODES) {
        g_off[i] = excl;
        g_cursor[i] = excl;
    }
}

__global__ void k_fill(const void* __restrict__ ei) {
    int e = blockIdx.x * blockDim.x + threadIdx.x;
    if (e < N_EDGES) {
        int src = load_idx(ei, e);
        int dst = load_idx(ei, (size_t)N_EDGES + e);
        if (src >= 0 && src < N_NODES && dst >= 0 && dst < N_NODES) {
            int p = atomicAdd(&g_cursor[dst], 1);
            g_srcs[p] = src;
        }
    }
}

// ---------------- mean propagation: warp per dst node ----------------
__global__ void __launch_bounds__(256) k_hop(const float* __restrict__ in,
                                             float* __restrict__ out) {
    int warp = (blockIdx.x * blockDim.x + threadIdx.x) >> 5;
    int lane = threadIdx.x & 31;
    if (warp >= N_NODES) return;

    int beg = g_off[warp];
    int end = g_off[warp + 1];

    float4 acc0 = make_float4(0.f, 0.f, 0.f, 0.f);
    float4 acc1 = make_float4(0.f, 0.f, 0.f, 0.f);

    int j = beg;
    for (; j + 1 < end; j += 2) {
        int s0 = g_srcs[j];
        int s1 = g_srcs[j + 1];
        float4 v0 = __ldg((const float4*)(in + (size_t)s0 * CH) + lane);
        float4 v1 = __ldg((const float4*)(in + (size_t)s1 * CH) + lane);
        acc0.x += v0.x; acc0.y += v0.y; acc0.z += v0.z; acc0.w += v0.w;
        acc1.x += v1.x; acc1.y += v1.y; acc1.z += v1.z; acc1.w += v1.w;
    }
    if (j < end) {
        int s0 = g_srcs[j];
        float4 v0 = __ldg((const float4*)(in + (size_t)s0 * CH) + lane);
        acc0.x += v0.x; acc0.y += v0.y; acc0.z += v0.z; acc0.w += v0.w;
    }

    int d = end - beg;
    float inv = 1.0f / (float)(d > 0 ? d : 1);
    float4 r;
    r.x = (acc0.x + acc1.x) * inv;
    r.y = (acc0.y + acc1.y) * inv;
    r.z = (acc0.z + acc1.z) * inv;
    r.w = (acc0.w + acc1.w) * inv;
    ((float4*)(out + (size_t)warp * CH))[lane] = r;
}

// ---------------- GEMM: out = h @ W^T + b ----------------
// Register-tiled: block tile 64 rows x 128 cols, K chunked by 32 via smem.
// 256 threads as 16x16; each thread computes 4 rows x 8 cols.
#define BM 64
#define KC 32
#define WSP 132   // padded stride for transposed W tile

__global__ void __launch_bounds__(256) k_gemm(
    const float* __restrict__ h, const float* __restrict__ W,
    const float* __restrict__ b, float* __restrict__ out) {
    __shared__ float Hs[BM * KC];       // 8 KB
    __shared__ float Ws[KC * WSP];      // 16.9 KB, Ws[k][o]

    const int t = threadIdx.x;
    const int tx = t & 15;              // output-col group (8 cols)
    const int ty = t >> 4;              // row group (4 rows)
    const int rb = blockIdx.x * BM;

    float4 bv0 = *(const float4*)(b + 8 * tx);
    float4 bv1 = *(const float4*)(b + 8 * tx + 4);
    float acc[4][8];
#pragma unroll
    for (int i = 0; i < 4; i++) {
        acc[i][0] = bv0.x; acc[i][1] = bv0.y; acc[i][2] = bv0.z; acc[i][3] = bv0.w;
        acc[i][4] = bv1.x; acc[i][5] = bv1.y; acc[i][6] = bv1.z; acc[i][7] = bv1.w;
    }

    for (int c = 0; c < CH / KC; c++) {
        const int k0 = c * KC;
        __syncthreads();
        // load Hs: 64 rows x 32 floats = 512 float4, 2 per thread
#pragma unroll
        for (int u = 0; u < 2; u++) {
            int idx = t + u * 256;              // 0..511
            int row = idx >> 3, j = idx & 7;
            int n = rb + row;
            float4 v = (n < N_NODES)
                ? *(const float4*)(h + (size_t)n * CH + k0 + j * 4)
                : make_float4(0.f, 0.f, 0.f, 0.f);
            *(float4*)(Hs + row * KC + j * 4) = v;
        }
        // load Ws transposed: 128 o x 8 float4(k) = 1024 units, 4 per thread
#pragma unroll
        for (int u = 0; u < 4; u++) {
            int idx = t + u * 256;              // 0..1023
            int o = idx >> 3, j = idx & 7;
            float4 v = *(const float4*)(W + (size_t)o * CH + k0 + j * 4);
            Ws[(j * 4 + 0) * WSP + o] = v.x;
            Ws[(j * 4 + 1) * WSP + o] = v.y;
            Ws[(j * 4 + 2) * WSP + o] = v.z;
            Ws[(j * 4 + 3) * WSP + o] = v.w;
        }
        __syncthreads();
#pragma unroll
        for (int k = 0; k < KC; k++) {
            float hv[4];
#pragma unroll
            for (int i = 0; i < 4; i++) hv[i] = Hs[(4 * ty + i) * KC + k];
            float4 w0 = *(const float4*)(Ws + k * WSP + 8 * tx);
            float4 w1 = *(const float4*)(Ws + k * WSP + 8 * tx + 4);
            float wv[8] = {w0.x, w0.y, w0.z, w0.w, w1.x, w1.y, w1.z, w1.w};
#pragma unroll
            for (int i = 0; i < 4; i++)
#pragma unroll
                for (int j = 0; j < 8; j++)
                    acc[i][j] = fmaf(hv[i], wv[j], acc[i][j]);
        }
    }

#pragma unroll
    for (int i = 0; i < 4; i++) {
        int n = rb + 4 * ty + i;
        if (n < N_NODES) {
            float4 o0 = make_float4(acc[i][0], acc[i][1], acc[i][2], acc[i][3]);
            float4 o1 = make_float4(acc[i][4], acc[i][5], acc[i][6], acc[i][7]);
            *(float4*)(out + (size_t)n * CH + 8 * tx) = o0;
            *(float4*)(out + (size_t)n * CH + 8 * tx + 4) = o1;
        }
    }
}

// ---------------- launcher ----------------
extern "C" void kernel_launch(void* const* d_in, const int* in_sizes, int n_in,
                              void* d_out, int out_size) {
    const float* x  = (const float*)d_in[0];
    const void*  ei = d_in[1];   // int32 or int64, detected on device
    const float* W  = (const float*)d_in[2];
    const float* b  = (const float*)d_in[3];
    float*       out = (float*)d_out;

    const int TB = 256;

    float* h1; float* h2;
    cudaGetSymbolAddress((void**)&h1, g_h1);
    cudaGetSymbolAddress((void**)&h2, g_h2);

    // CSR build (deterministic, capturable — kernel launches only)
    k_detect<<<1, 1>>>((const int*)ei);
    k_zero_deg<<<(N_NODES + TB - 1) / TB, TB>>>();
    k_degree<<<(N_EDGES + TB - 1) / TB, TB>>>(ei);
    k_scan1<<<N_SBLKS, 1024>>>();
    k_scan2<<<1, 128>>>();
    k_scan3<<<N_SBLKS, 1024>>>();
    k_fill<<<(N_EDGES + TB - 1) / TB, TB>>>(ei);

    // two mean-propagation hops
    int hopBlocks = (N_NODES + 8 - 1) / 8;  // 8 warps per block, warp per node
    k_hop<<<hopBlocks, TB>>>(x,  h1);
    k_hop<<<hopBlocks, TB>>>(h1, h2);

    // final linear (register-tiled)
    k_gemm<<<(N_NODES + BM - 1) / BM, 256>>>(h2, W, b, out);
}

// round 6
// speedup vs baseline: 2.3986x; 1.0802x over previous
#include <cuda_runtime.h>
#include <cuda_fp16.h>
#include <cuda_bf16.h>

#define N_NODES 100000
#define N_EDGES 1600000
#define CH      128   // in = out channels
#define N_SBLKS ((N_NODES + 1023) / 1024)   // 98

// ---------------- static scratch (no allocations allowed) ----------------
__device__ __half g_x16[(size_t)N_NODES * CH];
__device__ __half g_h1[(size_t)N_NODES * CH];
__device__ __half g_h2[(size_t)N_NODES * CH];
__device__ int    g_deg[N_NODES];
__device__ int    g_off[N_NODES + 1];
__device__ int    g_cursor[N_NODES];
__device__ int    g_srcs[N_EDGES];
__device__ int    g_part[128];
__device__ int    g_idx64;   // 1 if edge_index is int64, 0 if int32

// ---------------- dtype detection ----------------
__global__ void k_detect(const int* __restrict__ raw) {
    int nz = 0;
#pragma unroll
    for (int i = 0; i < 64; i++) {
        if (raw[2 * i + 1] != 0) nz++;
    }
    g_idx64 = (nz == 0) ? 1 : 0;
}

__device__ __forceinline__ int load_idx(const void* ei, size_t pos) {
    if (g_idx64) {
        return (int)((const long long*)ei)[pos];
    } else {
        return ((const int*)ei)[pos];
    }
}

// ---------------- CSR build ----------------
__global__ void k_zero_deg() {
    int i = blockIdx.x * blockDim.x + threadIdx.x;
    if (i < N_NODES) g_deg[i] = 0;
}

__global__ void k_degree(const void* __restrict__ ei) {
    int e = blockIdx.x * blockDim.x + threadIdx.x;
    if (e < N_EDGES) {
        int d = load_idx(ei, (size_t)N_EDGES + e);
        if (d >= 0 && d < N_NODES) atomicAdd(&g_deg[d], 1);
    }
}

__global__ void __launch_bounds__(1024) k_scan1() {
    int i = blockIdx.x * 1024 + threadIdx.x;
    int v = (i < N_NODES) ? g_deg[i] : 0;
#pragma unroll
    for (int o = 16; o; o >>= 1) v += __shfl_down_sync(0xffffffffu, v, o);
    __shared__ int ws[32];
    if ((threadIdx.x & 31) == 0) ws[threadIdx.x >> 5] = v;
    __syncthreads();
    if (threadIdx.x < 32) {
        int s = ws[threadIdx.x];
#pragma unroll
        for (int o = 16; o; o >>= 1) s += __shfl_down_sync(0xffffffffu, s, o);
        if (threadIdx.x == 0) g_part[blockIdx.x] = s;
    }
}

__global__ void k_scan2() {
    int t = threadIdx.x;  // 128 threads
    __shared__ int sm[128];
    int v = (t < N_SBLKS) ? g_part[t] : 0;
    sm[t] = v;
    __syncthreads();
    for (int o = 1; o < 128; o <<= 1) {
        int u = (t >= o) ? sm[t - o] : 0;
        __syncthreads();
        sm[t] += u;
        __syncthreads();
    }
    g_part[t] = sm[t] - v;
    if (t == 127) g_off[N_NODES] = sm[127];
}

__global__ void __launch_bounds__(1024) k_scan3() {
    int b = blockIdx.x, t = threadIdx.x;
    int i = b * 1024 + t;
    int lane = t & 31, w = t >> 5;
    int v = (i < N_NODES) ? g_deg[i] : 0;
    int s = v;
#pragma unroll
    for (int o = 1; o < 32; o <<= 1) {
        int u = __shfl_up_sync(0xffffffffu, s, o);
        if (lane >= o) s += u;
    }
    __shared__ int wsum[32];
    if (lane == 31) wsum[w] = s;
    __syncthreads();
    if (w == 0) {
        int ss = wsum[lane];
#pragma unroll
        for (int o = 1; o < 32; o <<= 1) {
            int u = __shfl_up_sync(0xffffffffu, ss, o);
            if (lane >= o) ss += u;
        }
        wsum[lane] = ss;
    }
    __syncthreads();
    int excl = (s - v) + ((w > 0) ? wsum[w - 1] : 0) + g_part[b];
    if (i < N_NODES) {
        g_off[i] = excl;
        g_cursor[i] = excl;
    }
}

__global__ void k_fill(const void* __restrict__ ei) {
    int e = blockIdx.x * blockDim.x + threadIdx.x;
    if (e < N_EDGES) {
        int src = load_idx(ei, e);
        int dst = load_idx(ei, (size_t)N_EDGES + e);
        if (src >= 0 && src < N_NODES && dst >= 0 && dst < N_NODES) {
            int p = atomicAdd(&g_cursor[dst], 1);
            g_srcs[p] = src;
        }
    }
}

// ---------------- x -> fp16 ----------------
__global__ void k_tofp16(const float* __restrict__ x) {
    int i = blockIdx.x * blockDim.x + threadIdx.x;   // over float4 units
    if (i < N_NODES * CH / 4) {
        float4 v = ((const float4*)x)[i];
        __half2 a = __floats2half2_rn(v.x, v.y);
        __half2 b = __floats2half2_rn(v.z, v.w);
        uint2 o;
        o.x = *(unsigned int*)&a;
        o.y = *(unsigned int*)&b;
        ((uint2*)g_x16)[i] = o;
    }
}

// ---------------- mean propagation (fp16 storage, fp32 accum) ----------------
// warp per dst node; lane handles 4 channels (8 bytes per edge row).
__global__ void __launch_bounds__(256) k_hop16(const __half* __restrict__ in,
                                               __half* __restrict__ out) {
    int warp = (blockIdx.x * blockDim.x + threadIdx.x) >> 5;
    int lane = threadIdx.x & 31;
    if (warp >= N_NODES) return;

    int beg = g_off[warp];
    int end = g_off[warp + 1];

    float4 acc0 = make_float4(0.f, 0.f, 0.f, 0.f);
    float4 acc1 = make_float4(0.f, 0.f, 0.f, 0.f);

    int j = beg;
    for (; j + 1 < end; j += 2) {
        int s0 = g_srcs[j];
        int s1 = g_srcs[j + 1];
        uint2 v0 = __ldg((const uint2*)(in + (size_t)s0 * CH) + lane);
        uint2 v1 = __ldg((const uint2*)(in + (size_t)s1 * CH) + lane);
        float2 p0 = __half22float2(*(__half2*)&v0.x);
        float2 q0 = __half22float2(*(__half2*)&v0.y);
        float2 p1 = __half22float2(*(__half2*)&v1.x);
        float2 q1 = __half22float2(*(__half2*)&v1.y);
        acc0.x += p0.x; acc0.y += p0.y; acc0.z += q0.x; acc0.w += q0.y;
        acc1.x += p1.x; acc1.y += p1.y; acc1.z += q1.x; acc1.w += q1.y;
    }
    if (j < end) {
        int s0 = g_srcs[j];
        uint2 v0 = __ldg((const uint2*)(in + (size_t)s0 * CH) + lane);
        float2 p0 = __half22float2(*(__half2*)&v0.x);
        float2 q0 = __half22float2(*(__half2*)&v0.y);
        acc0.x += p0.x; acc0.y += p0.y; acc0.z += q0.x; acc0.w += q0.y;
    }

    int d = end - beg;
    float inv = 1.0f / (float)(d > 0 ? d : 1);
    __half2 r0 = __floats2half2_rn((acc0.x + acc1.x) * inv, (acc0.y + acc1.y) * inv);
    __half2 r1 = __floats2half2_rn((acc0.z + acc1.z) * inv, (acc0.w + acc1.w) * inv);
    uint2 o;
    o.x = *(unsigned int*)&r0;
    o.y = *(unsigned int*)&r1;
    ((uint2*)(out + (size_t)warp * CH))[lane] = o;
}

// ---------------- GEMM: out = h @ W^T + b (packed f32x2 FFMA) ----------------
#define BM 64
#define KC 32
#define WSP 132   // padded stride for transposed W tile

__device__ __forceinline__ unsigned long long pack2(float lo, float hi) {
    unsigned long long r;
    asm("mov.b64 %0, {%1, %2};" : "=l"(r) : "f"(lo), "f"(hi));
    return r;
}
__device__ __forceinline__ float2 unpack2(unsigned long long v) {
    float2 f;
    asm("mov.b64 {%0, %1}, %2;" : "=f"(f.x), "=f"(f.y) : "l"(v));
    return f;
}
__device__ __forceinline__ void fma2(unsigned long long& d, unsigned long long a,
                                     unsigned long long b) {
    asm("fma.rn.f32x2 %0, %1, %2, %0;" : "+l"(d) : "l"(a), "l"(b));
}

__global__ void __launch_bounds__(256) k_gemm(
    const __half* __restrict__ h, const float* __restrict__ W,
    const float* __restrict__ b, float* __restrict__ out) {
    __shared__ float Hs[BM * KC];       // 8 KB
    __shared__ float Ws[KC * WSP];      // 16.9 KB, Ws[k][o]

    const int t = threadIdx.x;
    const int tx = t & 15;              // output-col group (8 cols)
    const int ty = t >> 4;              // row group (4 rows)
    const int rb = blockIdx.x * BM;

    float4 bv0 = *(const float4*)(b + 8 * tx);
    float4 bv1 = *(const float4*)(b + 8 * tx + 4);
    unsigned long long acc2[4][4];
#pragma unroll
    for (int i = 0; i < 4; i++) {
        acc2[i][0] = pack2(bv0.x, bv0.y);
        acc2[i][1] = pack2(bv0.z, bv0.w);
        acc2[i][2] = pack2(bv1.x, bv1.y);
        acc2[i][3] = pack2(bv1.z, bv1.w);
    }

    for (int c = 0; c < CH / KC; c++) {
        const int k0 = c * KC;
        __syncthreads();
        // load Hs (fp16 -> fp32): 64 rows x 32 halfs; each thread 8 halfs
        {
            int row = t >> 2;           // 0..63
            int j = t & 3;              // which 8-half group of the 32-chunk
            int n = rb + row;
            uint2 v = (n < N_NODES)
                ? *(const uint2*)(h + (size_t)n * CH + k0 + j * 8)
                : make_uint2(0u, 0u);
            __half2 h01 = *(__half2*)&v.x;
            __half2 h23 = *(__half2*)&v.y;
            float2 f01 = __half22float2(h01);
            float2 f23 = __half22float2(h23);
            float* dstp = Hs + row * KC + j * 8;
            // second uint2 covers halfs 4..7
            uint2 v2 = (n < N_NODES)
                ? *(const uint2*)(h + (size_t)n * CH + k0 + j * 8 + 4)
                : make_uint2(0u, 0u);
            float2 f45 = __half22float2(*(__half2*)&v2.x);
            float2 f67 = __half22float2(*(__half2*)&v2.y);
            dstp[0] = f01.x; dstp[1] = f01.y; dstp[2] = f23.x; dstp[3] = f23.y;
            dstp[4] = f45.x; dstp[5] = f45.y; dstp[6] = f67.x; dstp[7] = f67.y;
        }
        // load Ws transposed: 128 o x 8 float4(k) units = 1024, 4 per thread
#pragma unroll
        for (int u = 0; u < 4; u++) {
            int idx = t + u * 256;              // 0..1023
            int o = idx >> 3, j = idx & 7;
            float4 v = *(const float4*)(W + (size_t)o * CH + k0 + j * 4);
            Ws[(j * 4 + 0) * WSP + o] = v.x;
            Ws[(j * 4 + 1) * WSP + o] = v.y;
            Ws[(j * 4 + 2) * WSP + o] = v.z;
            Ws[(j * 4 + 3) * WSP + o] = v.w;
        }
        __syncthreads();
#pragma unroll
        for (int k = 0; k < KC; k++) {
            unsigned long long hp[4];
#pragma unroll
            for (int i = 0; i < 4; i++) {
                float hv = Hs[(4 * ty + i) * KC + k];
                hp[i] = pack2(hv, hv);
            }
            const unsigned long long* wp =
                (const unsigned long long*)(Ws + k * WSP + 8 * tx);
            unsigned long long w0 = wp[0], w1 = wp[1], w2 = wp[2], w3 = wp[3];
#pragma unroll
            for (int i = 0; i < 4; i++) {
                fma2(acc2[i][0], hp[i], w0);
                fma2(acc2[i][1], hp[i], w1);
                fma2(acc2[i][2], hp[i], w2);
                fma2(acc2[i][3], hp[i], w3);
            }
        }
    }

#pragma unroll
    for (int i = 0; i < 4; i++) {
        int n = rb + 4 * ty + i;
        if (n < N_NODES) {
            float2 a = unpack2(acc2[i][0]);
            float2 bb = unpack2(acc2[i][1]);
            float2 cc = unpack2(acc2[i][2]);
            float2 dd = unpack2(acc2[i][3]);
            float4 o0 = make_float4(a.x, a.y, bb.x, bb.y);
            float4 o1 = make_float4(cc.x, cc.y, dd.x, dd.y);
            *(float4*)(out + (size_t)n * CH + 8 * tx) = o0;
            *(float4*)(out + (size_t)n * CH + 8 * tx + 4) = o1;
        }
    }
}

// ---------------- launcher ----------------
extern "C" void kernel_launch(void* const* d_in, const int* in_sizes, int n_in,
                              void* d_out, int out_size) {
    const float* x  = (const float*)d_in[0];
    const void*  ei = d_in[1];   // int32 or int64, detected on device
    const float* W  = (const float*)d_in[2];
    const float* b  = (const float*)d_in[3];
    float*       out = (float*)d_out;

    const int TB = 256;

    __half* x16; __half* h1; __half* h2;
    cudaGetSymbolAddress((void**)&x16, g_x16);
    cudaGetSymbolAddress((void**)&h1, g_h1);
    cudaGetSymbolAddress((void**)&h2, g_h2);

    // CSR build (kernel launches only)
    k_detect<<<1, 1>>>((const int*)ei);
    k_zero_deg<<<(N_NODES + TB - 1) / TB, TB>>>();
    k_degree<<<(N_EDGES + TB - 1) / TB, TB>>>(ei);
    k_scan1<<<N_SBLKS, 1024>>>();
    k_scan2<<<1, 128>>>();
    k_scan3<<<N_SBLKS, 1024>>>();
    k_fill<<<(N_EDGES + TB - 1) / TB, TB>>>(ei);

    // x -> fp16
    k_tofp16<<<(N_NODES * CH / 4 + TB - 1) / TB, TB>>>(x);

    // two mean-propagation hops (fp16 storage)
    int hopBlocks = (N_NODES + 8 - 1) / 8;  // 8 warps/block, warp per node
    k_hop16<<<hopBlocks, TB>>>(x16, h1);
    k_hop16<<<hopBlocks, TB>>>(h1, h2);

    // final linear (packed f32x2)
    k_gemm<<<(N_NODES + BM - 1) / BM, 256>>>(h2, W, b, out);
}

// round 8
// speedup vs baseline: 3.2514x; 1.3555x over previous
#include <cuda_runtime.h>
#include <cuda_fp16.h>
#include <cuda_bf16.h>

#define N_NODES 100000
#define N_EDGES 1600000
#define CH      128   // in = out channels
#define N_SBLKS ((N_NODES + 1023) / 1024)   // 98

// ---------------- static scratch (no allocations allowed) ----------------
__device__ __half g_x16[(size_t)N_NODES * CH];
__device__ __half g_h1[(size_t)N_NODES * CH];
__device__ __half g_h2[(size_t)N_NODES * CH];
__device__ __half g_w16[CH * CH];
__device__ int    g_deg[N_NODES];
__device__ int    g_off[N_NODES + 1];
__device__ int    g_cursor[N_NODES];
__device__ int    g_srcs[N_EDGES];
__device__ int    g_part[128];
__device__ int    g_idx64;   // 1 if edge_index is int64, 0 if int32

// ---------------- dtype detection ----------------
__global__ void k_detect(const int* __restrict__ raw) {
    int nz = 0;
#pragma unroll
    for (int i = 0; i < 64; i++) {
        if (raw[2 * i + 1] != 0) nz++;
    }
    g_idx64 = (nz == 0) ? 1 : 0;
}

__device__ __forceinline__ int load_idx(const void* ei, size_t pos) {
    if (g_idx64) {
        return (int)((const long long*)ei)[pos];
    } else {
        return ((const int*)ei)[pos];
    }
}

// ---------------- CSR build ----------------
__global__ void k_zero_deg() {
    int i = blockIdx.x * blockDim.x + threadIdx.x;
    if (i < N_NODES) g_deg[i] = 0;
}

__global__ void k_degree(const void* __restrict__ ei) {
    int e = blockIdx.x * blockDim.x + threadIdx.x;
    if (e < N_EDGES) {
        int d = load_idx(ei, (size_t)N_EDGES + e);
        if (d >= 0 && d < N_NODES) atomicAdd(&g_deg[d], 1);
    }
}

__global__ void __launch_bounds__(1024) k_scan1() {
    int i = blockIdx.x * 1024 + threadIdx.x;
    int v = (i < N_NODES) ? g_deg[i] : 0;
#pragma unroll
    for (int o = 16; o; o >>= 1) v += __shfl_down_sync(0xffffffffu, v, o);
    __shared__ int ws[32];
    if ((threadIdx.x & 31) == 0) ws[threadIdx.x >> 5] = v;
    __syncthreads();
    if (threadIdx.x < 32) {
        int s = ws[threadIdx.x];
#pragma unroll
        for (int o = 16; o; o >>= 1) s += __shfl_down_sync(0xffffffffu, s, o);
        if (threadIdx.x == 0) g_part[blockIdx.x] = s;
    }
}

__global__ void k_scan2() {
    int t = threadIdx.x;  // 128 threads
    __shared__ int sm[128];
    int v = (t < N_SBLKS) ? g_part[t] : 0;
    sm[t] = v;
    __syncthreads();
    for (int o = 1; o < 128; o <<= 1) {
        int u = (t >= o) ? sm[t - o] : 0;
        __syncthreads();
        sm[t] += u;
        __syncthreads();
    }
    g_part[t] = sm[t] - v;
    if (t == 127) g_off[N_NODES] = sm[127];
}

__global__ void __launch_bounds__(1024) k_scan3() {
    int b = blockIdx.x, t = threadIdx.x;
    int i = b * 1024 + t;
    int lane = t & 31, w = t >> 5;
    int v = (i < N_NODES) ? g_deg[i] : 0;
    int s = v;
#pragma unroll
    for (int o = 1; o < 32; o <<= 1) {
        int u = __shfl_up_sync(0xffffffffu, s, o);
        if (lane >= o) s += u;
    }
    __shared__ int wsum[32];
    if (lane == 31) wsum[w] = s;
    __syncthreads();
    if (w == 0) {
        int ss = wsum[lane];
#pragma unroll
        for (int o = 1; o < 32; o <<= 1) {
            int u = __shfl_up_sync(0xffffffffu, ss, o);
            if (lane >= o) ss += u;
        }
        wsum[lane] = ss;
    }
    __syncthreads();
    int excl = (s - v) + ((w > 0) ? wsum[w - 1] : 0) + g_part[b];
    if (i < N_NODES) {
        g_off[i] = excl;
        g_cursor[i] = excl;
    }
}

__global__ void k_fill(const void* __restrict__ ei) {
    int e = blockIdx.x * blockDim.x + threadIdx.x;
    if (e < N_EDGES) {
        int src = load_idx(ei, e);
        int dst = load_idx(ei, (size_t)N_EDGES + e);
        if (src >= 0 && src < N_NODES && dst >= 0 && dst < N_NODES) {
            int p = atomicAdd(&g_cursor[dst], 1);
            g_srcs[p] = src;
        }
    }
}

// ---------------- fp32 -> fp16 conversions ----------------
__global__ void k_tofp16(const float* __restrict__ x) {
    int i = blockIdx.x * blockDim.x + threadIdx.x;   // over float4 units
    if (i < N_NODES * CH / 4) {
        float4 v = ((const float4*)x)[i];
        __half2 a = __floats2half2_rn(v.x, v.y);
        __half2 b = __floats2half2_rn(v.z, v.w);
        uint2 o;
        o.x = *(unsigned int*)&a;
        o.y = *(unsigned int*)&b;
        ((uint2*)g_x16)[i] = o;
    }
}

__global__ void k_w16(const float* __restrict__ W) {
    int i = blockIdx.x * blockDim.x + threadIdx.x;   // over float2 units
    if (i < CH * CH / 2) {
        float2 v = ((const float2*)W)[i];
        __half2 a = __floats2half2_rn(v.x, v.y);
        ((unsigned int*)g_w16)[i] = *(unsigned int*)&a;
    }
}

// ---------------- mean propagation (fp16 storage, fp32 accum) ----------------
// warp per dst node; lane handles 4 channels (8 bytes per edge row); unroll 4.
__global__ void __launch_bounds__(256) k_hop16(const __half* __restrict__ in,
                                               __half* __restrict__ out) {
    int warp = (blockIdx.x * blockDim.x + threadIdx.x) >> 5;
    int lane = threadIdx.x & 31;
    if (warp >= N_NODES) return;

    int beg = g_off[warp];
    int end = g_off[warp + 1];

    float4 acc[4];
#pragma unroll
    for (int i = 0; i < 4; i++) acc[i] = make_float4(0.f, 0.f, 0.f, 0.f);

    int j = beg;
    for (; j + 3 < end; j += 4) {
        uint2 v[4];
#pragma unroll
        for (int u = 0; u < 4; u++) {
            int s = g_srcs[j + u];
            v[u] = __ldg((const uint2*)(in + (size_t)s * CH) + lane);
        }
#pragma unroll
        for (int u = 0; u < 4; u++) {
            float2 p = __half22float2(*(__half2*)&v[u].x);
            float2 q = __half22float2(*(__half2*)&v[u].y);
            acc[u].x += p.x; acc[u].y += p.y; acc[u].z += q.x; acc[u].w += q.y;
        }
    }
    for (; j < end; j++) {
        int s = g_srcs[j];
        uint2 v0 = __ldg((const uint2*)(in + (size_t)s * CH) + lane);
        float2 p = __half22float2(*(__half2*)&v0.x);
        float2 q = __half22float2(*(__half2*)&v0.y);
        acc[0].x += p.x; acc[0].y += p.y; acc[0].z += q.x; acc[0].w += q.y;
    }

    int d = end - beg;
    float inv = 1.0f / (float)(d > 0 ? d : 1);
    float4 r;
    r.x = (acc[0].x + acc[1].x + acc[2].x + acc[3].x) * inv;
    r.y = (acc[0].y + acc[1].y + acc[2].y + acc[3].y) * inv;
    r.z = (acc[0].z + acc[1].z + acc[2].z + acc[3].z) * inv;
    r.w = (acc[0].w + acc[1].w + acc[2].w + acc[3].w) * inv;
    __half2 r0 = __floats2half2_rn(r.x, r.y);
    __half2 r1 = __floats2half2_rn(r.z, r.w);
    uint2 o;
    o.x = *(unsigned int*)&r0;
    o.y = *(unsigned int*)&r1;
    ((uint2*)(out + (size_t)warp * CH))[lane] = o;
}

// ---------------- GEMM via tensor cores: out = h @ W^T + b ----------------
// mma.sync m16n8k16 fp16xfp16 + fp32 accum.
// Block: 128 threads = 4 warps. Tile: 64 rows x 128 cols (full N), K=128.
// Hs 64x128 fp16 (16KB) + Wsm 128x128 fp16 (32KB) = 48KB static smem.
// Rows are 256 bytes = 16 chunks of 16B; chunk index XOR-swizzled by (row&7).
#define GBM 64

__global__ void __launch_bounds__(128) k_gemm_mma(
    const __half* __restrict__ h, const float* __restrict__ bias,
    float* __restrict__ out) {
    __shared__ __half Hs[GBM * CH];   // 16 KB (swizzled)
    __shared__ __half Wsm[CH * CH];   // 32 KB (swizzled)

    const int t = threadIdx.x;
    const int warp = t >> 5;
    const int lane = t & 31;
    const int gid = lane >> 2;        // 0..7
    const int tg = lane & 3;          // 0..3
    const int rb = blockIdx.x * GBM;

    // fill Hs: 64 rows x 16 chunks of 16B (row = 128 fp16 = 256 B)
    for (int i = t; i < GBM * 16; i += 128) {
        int r = i >> 4, c = i & 15;
        int n = rb + r;
        uint4 v = make_uint4(0u, 0u, 0u, 0u);
        if (n < N_NODES) v = ((const uint4*)(h + (size_t)n * CH))[c];
        ((uint4*)Hs)[(r << 4) | (c ^ (r & 7))] = v;
    }
    // fill Wsm: 128 rows x 16 chunks
    for (int i = t; i < CH * 16; i += 128) {
        int r = i >> 4, c = i & 15;
        uint4 v = ((const uint4*)g_w16)[i];
        ((uint4*)Wsm)[(r << 4) | (c ^ (r & 7))] = v;
    }
    __syncthreads();

    // accumulators: 16 n-tiles x 4 floats
    float acc[16][4];
#pragma unroll
    for (int nt = 0; nt < 16; nt++)
#pragma unroll
        for (int i = 0; i < 4; i++) acc[nt][i] = 0.f;

    const int wr = warp * 16;                    // warp's row strip in Hs
    const char* HsB = (const char*)Hs;
    const char* WsB = (const char*)Wsm;

#pragma unroll
    for (int ks = 0; ks < 8; ks++) {             // k16 steps
        // A fragment (m16k16): rows wr+gid / wr+gid+8, k-halves via chunks
        int rA0 = wr + gid, rA1 = rA0 + 8;
        int cA0 = ks * 2, cA1 = ks * 2 + 1;      // chunk indices (16B = 8 halves)
        unsigned a0 = *(const unsigned*)(HsB + rA0 * 256 + ((cA0 ^ (rA0 & 7)) << 4) + tg * 4);
        unsigned a1 = *(const unsigned*)(HsB + rA1 * 256 + ((cA0 ^ (rA1 & 7)) << 4) + tg * 4);
        unsigned a2 = *(const unsigned*)(HsB + rA0 * 256 + ((cA1 ^ (rA0 & 7)) << 4) + tg * 4);
        unsigned a3 = *(const unsigned*)(HsB + rA1 * 256 + ((cA1 ^ (rA1 & 7)) << 4) + tg * 4);

#pragma unroll
        for (int nt = 0; nt < 16; nt++) {
            int n = nt * 8 + gid;
            unsigned b0 = *(const unsigned*)(WsB + n * 256 + ((cA0 ^ (n & 7)) << 4) + tg * 4);
            unsigned b1 = *(const unsigned*)(WsB + n * 256 + ((cA1 ^ (n & 7)) << 4) + tg * 4);
            asm volatile(
                "mma.sync.aligned.m16n8k16.row.col.f32.f16.f16.f32 "
                "{%0,%1,%2,%3}, {%4,%5,%6,%7}, {%8,%9}, {%0,%1,%2,%3};"
                : "+f"(acc[nt][0]), "+f"(acc[nt][1]),
                  "+f"(acc[nt][2]), "+f"(acc[nt][3])
                : "r"(a0), "r"(a1), "r"(a2), "r"(a3), "r"(b0), "r"(b1));
        }
    }

    // epilogue: add bias, store
    int row0 = rb + wr + gid;
    int row1 = row0 + 8;
#pragma unroll
    for (int nt = 0; nt < 16; nt++) {
        int col = nt * 8 + 2 * tg;
        float2 bv = *(const float2*)(bias + col);
        if (row0 < N_NODES) {
            float2 o = make_float2(acc[nt][0] + bv.x, acc[nt][1] + bv.y);
            *(float2*)(out + (size_t)row0 * CH + col) = o;
        }
        if (row1 < N_NODES) {
            float2 o = make_float2(acc[nt][2] + bv.x, acc[nt][3] + bv.y);
            *(float2*)(out + (size_t)row1 * CH + col) = o;
        }
    }
}

// ---------------- launcher ----------------
extern "C" void kernel_launch(void* const* d_in, const int* in_sizes, int n_in,
                              void* d_out, int out_size) {
    const float* x  = (const float*)d_in[0];
    const void*  ei = d_in[1];   // int32 or int64, detected on device
    const float* W  = (const float*)d_in[2];
    const float* b  = (const float*)d_in[3];
    float*       out = (float*)d_out;

    const int TB = 256;

    __half* x16; __half* h1; __half* h2;
    cudaGetSymbolAddress((void**)&x16, g_x16);
    cudaGetSymbolAddress((void**)&h1, g_h1);
    cudaGetSymbolAddress((void**)&h2, g_h2);

    // CSR build (kernel launches only)
    k_detect<<<1, 1>>>((const int*)ei);
    k_zero_deg<<<(N_NODES + TB - 1) / TB, TB>>>();
    k_degree<<<(N_EDGES + TB - 1) / TB, TB>>>(ei);
    k_scan1<<<N_SBLKS, 1024>>>();
    k_scan2<<<1, 128>>>();
    k_scan3<<<N_SBLKS, 1024>>>();
    k_fill<<<(N_EDGES + TB - 1) / TB, TB>>>(ei);

    // conversions
    k_tofp16<<<(N_NODES * CH / 4 + TB - 1) / TB, TB>>>(x);
    k_w16<<<(CH * CH / 2 + TB - 1) / TB, TB>>>(W);

    // two mean-propagation hops (fp16 storage)
    int hopBlocks = (N_NODES + 8 - 1) / 8;  // 8 warps/block, warp per node
    k_hop16<<<hopBlocks, TB>>>(x16, h1);
    k_hop16<<<hopBlocks, TB>>>(h1, h2);

    // final linear (tensor cores)
    k_gemm_mma<<<(N_NODES + GBM - 1) / GBM, 128>>>(h2, b, out);
}

// round 9
// speedup vs baseline: 3.4254x; 1.0535x over previous
#include <cuda_runtime.h>
#include <cuda_fp16.h>
#include <cuda_bf16.h>

#define N_NODES 100000
#define N_EDGES 1600000
#define CH      128   // in = out channels
#define N_SBLKS ((N_NODES + 1023) / 1024)   // 98

// ---------------- static scratch (no allocations allowed) ----------------
__device__ __half g_y16[(size_t)N_NODES * CH];   // fp16(x @ W^T)
__device__ __half g_h1[(size_t)N_NODES * CH];    // after hop 1
__device__ __half g_w16[CH * CH];
__device__ int    g_deg[N_NODES];
__device__ int    g_off[N_NODES + 1];
__device__ int    g_cursor[N_NODES];
__device__ int    g_srcs[N_EDGES];
__device__ int    g_part[128];
__device__ int    g_idx64;   // 1 if edge_index is int64, 0 if int32

// ---------------- prep: zero degrees + dtype detect + W -> fp16 ----------------
// blocks [0, ZB): zero g_deg; blocks [ZB, ZB+WB): convert W; block 0 thread 0: detect.
#define ZB ((N_NODES + 255) / 256)          // 391
#define WB ((CH * CH / 2 + 255) / 256)      // 32

__global__ void k_prep(const int* __restrict__ raw, const float* __restrict__ W) {
    if (blockIdx.x < ZB) {
        int i = blockIdx.x * 256 + threadIdx.x;
        if (i < N_NODES) g_deg[i] = 0;
        if (blockIdx.x == 0 && threadIdx.x == 0) {
            int nz = 0;
#pragma unroll
            for (int k = 0; k < 64; k++) {
                if (raw[2 * k + 1] != 0) nz++;
            }
            g_idx64 = (nz == 0) ? 1 : 0;
        }
    } else {
        int i = (blockIdx.x - ZB) * 256 + threadIdx.x;   // over float2 units
        if (i < CH * CH / 2) {
            float2 v = ((const float2*)W)[i];
            __half2 a = __floats2half2_rn(v.x, v.y);
            ((unsigned int*)g_w16)[i] = *(unsigned int*)&a;
        }
    }
}

__device__ __forceinline__ int load_idx(const void* ei, size_t pos) {
    if (g_idx64) {
        return (int)((const long long*)ei)[pos];
    } else {
        return ((const int*)ei)[pos];
    }
}

// ---------------- CSR build ----------------
__global__ void k_degree(const void* __restrict__ ei) {
    int e = blockIdx.x * blockDim.x + threadIdx.x;
    if (e < N_EDGES) {
        int d = load_idx(ei, (size_t)N_EDGES + e);
        if (d >= 0 && d < N_NODES) atomicAdd(&g_deg[d], 1);
    }
}

__global__ void __launch_bounds__(1024) k_scan1() {
    int i = blockIdx.x * 1024 + threadIdx.x;
    int v = (i < N_NODES) ? g_deg[i] : 0;
#pragma unroll
    for (int o = 16; o; o >>= 1) v += __shfl_down_sync(0xffffffffu, v, o);
    __shared__ int ws[32];
    if ((threadIdx.x & 31) == 0) ws[threadIdx.x >> 5] = v;
    __syncthreads();
    if (threadIdx.x < 32) {
        int s = ws[threadIdx.x];
#pragma unroll
        for (int o = 16; o; o >>= 1) s += __shfl_down_sync(0xffffffffu, s, o);
        if (threadIdx.x == 0) g_part[blockIdx.x] = s;
    }
}

__global__ void k_scan2() {
    int t = threadIdx.x;  // 128 threads
    __shared__ int sm[128];
    int v = (t < N_SBLKS) ? g_part[t] : 0;
    sm[t] = v;
    __syncthreads();
    for (int o = 1; o < 128; o <<= 1) {
        int u = (t >= o) ? sm[t - o] : 0;
        __syncthreads();
        sm[t] += u;
        __syncthreads();
    }
    g_part[t] = sm[t] - v;
    if (t == 127) g_off[N_NODES] = sm[127];
}

__global__ void __launch_bounds__(1024) k_scan3() {
    int b = blockIdx.x, t = threadIdx.x;
    int i = b * 1024 + t;
    int lane = t & 31, w = t >> 5;
    int v = (i < N_NODES) ? g_deg[i] : 0;
    int s = v;
#pragma unroll
    for (int o = 1; o < 32; o <<= 1) {
        int u = __shfl_up_sync(0xffffffffu, s, o);
        if (lane >= o) s += u;
    }
    __shared__ int wsum[32];
    if (lane == 31) wsum[w] = s;
    __syncthreads();
    if (w == 0) {
        int ss = wsum[lane];
#pragma unroll
        for (int o = 1; o < 32; o <<= 1) {
            int u = __shfl_up_sync(0xffffffffu, ss, o);
            if (lane >= o) ss += u;
        }
        wsum[lane] = ss;
    }
    __syncthreads();
    int excl = (s - v) + ((w > 0) ? wsum[w - 1] : 0) + g_part[b];
    if (i < N_NODES) {
        g_off[i] = excl;
        g_cursor[i] = excl;
    }
}

__global__ void k_fill(const void* __restrict__ ei) {
    int e = blockIdx.x * blockDim.x + threadIdx.x;
    if (e < N_EDGES) {
        int src = load_idx(ei, e);
        int dst = load_idx(ei, (size_t)N_EDGES + e);
        if (src >= 0 && src < N_NODES && dst >= 0 && dst < N_NODES) {
            int p = atomicAdd(&g_cursor[dst], 1);
            g_srcs[p] = src;
        }
    }
}

// ---------------- GEMM via tensor cores: y16 = fp16(x @ W^T) ----------------
// x is fp32 in gmem; converted to fp16 during the smem fill.
// mma.sync m16n8k16. 128 threads = 4 warps, tile 64 rows x 128 cols, K=128.
// Hs 16KB + Wsm 32KB = 48KB static smem. Rows = 16 chunks of 16B, XOR-swizzled.
#define GBM 64

__global__ void __launch_bounds__(128) k_gemm_x(
    const float* __restrict__ x, __half* __restrict__ y) {
    __shared__ __half Hs[GBM * CH];   // 16 KB (swizzled)
    __shared__ __half Wsm[CH * CH];   // 32 KB (swizzled)

    const int t = threadIdx.x;
    const int warp = t >> 5;
    const int lane = t & 31;
    const int gid = lane >> 2;        // 0..7
    const int tg = lane & 3;          // 0..3
    const int rb = blockIdx.x * GBM;

    // fill Hs from fp32 x: 64 rows x 16 chunks (chunk = 8 halves = 8 floats src)
    for (int i = t; i < GBM * 16; i += 128) {
        int r = i >> 4, c = i & 15;
        int n = rb + r;
        uint4 o = make_uint4(0u, 0u, 0u, 0u);
        if (n < N_NODES) {
            const float4* xr = (const float4*)(x + (size_t)n * CH + c * 8);
            float4 f0 = xr[0];
            float4 f1 = xr[1];
            __half2 h0 = __floats2half2_rn(f0.x, f0.y);
            __half2 h1 = __floats2half2_rn(f0.z, f0.w);
            __half2 h2 = __floats2half2_rn(f1.x, f1.y);
            __half2 h3 = __floats2half2_rn(f1.z, f1.w);
            o.x = *(unsigned*)&h0; o.y = *(unsigned*)&h1;
            o.z = *(unsigned*)&h2; o.w = *(unsigned*)&h3;
        }
        ((uint4*)Hs)[(r << 4) | (c ^ (r & 7))] = o;
    }
    // fill Wsm: 128 rows x 16 chunks
    for (int i = t; i < CH * 16; i += 128) {
        int r = i >> 4, c = i & 15;
        uint4 v = ((const uint4*)g_w16)[i];
        ((uint4*)Wsm)[(r << 4) | (c ^ (r & 7))] = v;
    }
    __syncthreads();

    float acc[16][4];
#pragma unroll
    for (int nt = 0; nt < 16; nt++)
#pragma unroll
        for (int i = 0; i < 4; i++) acc[nt][i] = 0.f;

    const int wr = warp * 16;
    const char* HsB = (const char*)Hs;
    const char* WsB = (const char*)Wsm;

#pragma unroll
    for (int ks = 0; ks < 8; ks++) {
        int rA0 = wr + gid, rA1 = rA0 + 8;
        int cA0 = ks * 2, cA1 = ks * 2 + 1;
        unsigned a0 = *(const unsigned*)(HsB + rA0 * 256 + ((cA0 ^ (rA0 & 7)) << 4) + tg * 4);
        unsigned a1 = *(const unsigned*)(HsB + rA1 * 256 + ((cA0 ^ (rA1 & 7)) << 4) + tg * 4);
        unsigned a2 = *(const unsigned*)(HsB + rA0 * 256 + ((cA1 ^ (rA0 & 7)) << 4) + tg * 4);
        unsigned a3 = *(const unsigned*)(HsB + rA1 * 256 + ((cA1 ^ (rA1 & 7)) << 4) + tg * 4);

#pragma unroll
        for (int nt = 0; nt < 16; nt++) {
            int n = nt * 8 + gid;
            unsigned b0 = *(const unsigned*)(WsB + n * 256 + ((cA0 ^ (n & 7)) << 4) + tg * 4);
            unsigned b1 = *(const unsigned*)(WsB + n * 256 + ((cA1 ^ (n & 7)) << 4) + tg * 4);
            asm volatile(
                "mma.sync.aligned.m16n8k16.row.col.f32.f16.f16.f32 "
                "{%0,%1,%2,%3}, {%4,%5,%6,%7}, {%8,%9}, {%0,%1,%2,%3};"
                : "+f"(acc[nt][0]), "+f"(acc[nt][1]),
                  "+f"(acc[nt][2]), "+f"(acc[nt][3])
                : "r"(a0), "r"(a1), "r"(a2), "r"(a3), "r"(b0), "r"(b1));
        }
    }

    // epilogue: store fp16 y (no bias here — bias added after hops)
    int row0 = rb + wr + gid;
    int row1 = row0 + 8;
#pragma unroll
    for (int nt = 0; nt < 16; nt++) {
        int col = nt * 8 + 2 * tg;
        if (row0 < N_NODES) {
            __half2 o = __floats2half2_rn(acc[nt][0], acc[nt][1]);
            *(__half2*)(y + (size_t)row0 * CH + col) = o;
        }
        if (row1 < N_NODES) {
            __half2 o = __floats2half2_rn(acc[nt][2], acc[nt][3]);
            *(__half2*)(y + (size_t)row1 * CH + col) = o;
        }
    }
}

// ---------------- mean propagation (fp16 -> fp16), warp per dst node ----------------
__global__ void __launch_bounds__(256) k_hop_mid(const __half* __restrict__ in,
                                                 __half* __restrict__ out) {
    int warp = (blockIdx.x * blockDim.x + threadIdx.x) >> 5;
    int lane = threadIdx.x & 31;
    if (warp >= N_NODES) return;

    int beg = g_off[warp];
    int end = g_off[warp + 1];

    float4 acc[4];
#pragma unroll
    for (int i = 0; i < 4; i++) acc[i] = make_float4(0.f, 0.f, 0.f, 0.f);

    int j = beg;
    for (; j + 3 < end; j += 4) {
        uint2 v[4];
#pragma unroll
        for (int u = 0; u < 4; u++) {
            int s = g_srcs[j + u];
            v[u] = __ldg((const uint2*)(in + (size_t)s * CH) + lane);
        }
#pragma unroll
        for (int u = 0; u < 4; u++) {
            float2 p = __half22float2(*(__half2*)&v[u].x);
            float2 q = __half22float2(*(__half2*)&v[u].y);
            acc[u].x += p.x; acc[u].y += p.y; acc[u].z += q.x; acc[u].w += q.y;
        }
    }
    for (; j < end; j++) {
        int s = g_srcs[j];
        uint2 v0 = __ldg((const uint2*)(in + (size_t)s * CH) + lane);
        float2 p = __half22float2(*(__half2*)&v0.x);
        float2 q = __half22float2(*(__half2*)&v0.y);
        acc[0].x += p.x; acc[0].y += p.y; acc[0].z += q.x; acc[0].w += q.y;
    }

    int d = end - beg;
    float inv = 1.0f / (float)(d > 0 ? d : 1);
    float4 r;
    r.x = (acc[0].x + acc[1].x + acc[2].x + acc[3].x) * inv;
    r.y = (acc[0].y + acc[1].y + acc[2].y + acc[3].y) * inv;
    r.z = (acc[0].z + acc[1].z + acc[2].z + acc[3].z) * inv;
    r.w = (acc[0].w + acc[1].w + acc[2].w + acc[3].w) * inv;
    __half2 r0 = __floats2half2_rn(r.x, r.y);
    __half2 r1 = __floats2half2_rn(r.z, r.w);
    uint2 o;
    o.x = *(unsigned int*)&r0;
    o.y = *(unsigned int*)&r1;
    ((uint2*)(out + (size_t)warp * CH))[lane] = o;
}

// ---------------- final hop: fp16 in -> fp32 out, bias fused ----------------
__global__ void __launch_bounds__(256) k_hop_last(const __half* __restrict__ in,
                                                  const float* __restrict__ bias,
                                                  float* __restrict__ out) {
    int warp = (blockIdx.x * blockDim.x + threadIdx.x) >> 5;
    int lane = threadIdx.x & 31;
    if (warp >= N_NODES) return;

    int beg = g_off[warp];
    int end = g_off[warp + 1];

    float4 acc[4];
#pragma unroll
    for (int i = 0; i < 4; i++) acc[i] = make_float4(0.f, 0.f, 0.f, 0.f);

    int j = beg;
    for (; j + 3 < end; j += 4) {
        uint2 v[4];
#pragma unroll
        for (int u = 0; u < 4; u++) {
            int s = g_srcs[j + u];
            v[u] = __ldg((const uint2*)(in + (size_t)s * CH) + lane);
        }
#pragma unroll
        for (int u = 0; u < 4; u++) {
            float2 p = __half22float2(*(__half2*)&v[u].x);
            float2 q = __half22float2(*(__half2*)&v[u].y);
            acc[u].x += p.x; acc[u].y += p.y; acc[u].z += q.x; acc[u].w += q.y;
        }
    }
    for (; j < end; j++) {
        int s = g_srcs[j];
        uint2 v0 = __ldg((const uint2*)(in + (size_t)s * CH) + lane);
        float2 p = __half22float2(*(__half2*)&v0.x);
        float2 q = __half22float2(*(__half2*)&v0.y);
        acc[0].x += p.x; acc[0].y += p.y; acc[0].z += q.x; acc[0].w += q.y;
    }

    int d = end - beg;
    float inv = 1.0f / (float)(d > 0 ? d : 1);
    float4 bv = __ldg((const float4*)bias + lane);
    float4 r;
    r.x = (acc[0].x + acc[1].x + acc[2].x + acc[3].x) * inv + bv.x;
    r.y = (acc[0].y + acc[1].y + acc[2].y + acc[3].y) * inv + bv.y;
    r.z = (acc[0].z + acc[1].z + acc[2].z + acc[3].z) * inv + bv.z;
    r.w = (acc[0].w + acc[1].w + acc[2].w + acc[3].w) * inv + bv.w;
    ((float4*)(out + (size_t)warp * CH))[lane] = r;
}

// ---------------- launcher ----------------
extern "C" void kernel_launch(void* const* d_in, const int* in_sizes, int n_in,
                              void* d_out, int out_size) {
    const float* x  = (const float*)d_in[0];
    const void*  ei = d_in[1];   // int32 or int64, detected on device
    const float* W  = (const float*)d_in[2];
    const float* b  = (const float*)d_in[3];
    float*       out = (float*)d_out;

    const int TB = 256;

    __half* y16; __half* h1;
    cudaGetSymbolAddress((void**)&y16, g_y16);
    cudaGetSymbolAddress((void**)&h1, g_h1);

    // prep (zero deg + detect + W->fp16) then CSR build
    k_prep<<<ZB + WB, 256>>>((const int*)ei, W);
    k_degree<<<(N_EDGES + TB - 1) / TB, TB>>>(ei);
    k_scan1<<<N_SBLKS, 1024>>>();
    k_scan2<<<1, 128>>>();
    k_scan3<<<N_SBLKS, 1024>>>();
    k_fill<<<(N_EDGES + TB - 1) / TB, TB>>>(ei);

    // y16 = fp16(x @ W^T)  (commutes with propagation)
    k_gemm_x<<<(N_NODES + GBM - 1) / GBM, 128>>>(x, y16);

    // two mean-propagation hops; bias fused into the last one
    int hopBlocks = (N_NODES + 8 - 1) / 8;  // 8 warps/block, warp per node
    k_hop_mid<<<hopBlocks, TB>>>(y16, h1);
    k_hop_last<<<hopBlocks, TB>>>(h1, b, out);
}